// round 1
// baseline (speedup 1.0000x reference)
#include <cuda_runtime.h>

#define D_MODEL 1024
#define KV_DIM 256
#define N_HEADS 16
#define N_GROUPS 4
#define HEAD_DIM 64
#define TSEQ 2048
#define BATCH 2
#define BT (BATCH * TSEQ)

// Scratch buffers (static device globals; no allocation in kernel_launch).
__device__ float g_Q[(size_t)BT * D_MODEL];
__device__ float g_K[(size_t)BT * KV_DIM];
__device__ float g_V[(size_t)BT * KV_DIM];
__device__ float g_O[(size_t)BT * D_MODEL];

// ---------------------------------------------------------------------------
// SGEMM: C[M,N] = A[M,K] @ W[K,N] + bias[N]
// 128x128x16 tiles, 256 threads, 8x8 micro-tile per thread.
// ---------------------------------------------------------------------------
#define GBM 128
#define GBN 128
#define GBK 16

__global__ __launch_bounds__(256) void sgemm_bias(
    const float* __restrict__ A, const float* __restrict__ W,
    const float* __restrict__ bias, float* __restrict__ C,
    int M, int N, int K)
{
    __shared__ float As[GBK][GBM + 4];  // transposed A tile: As[k][m]
    __shared__ float Ws[GBK][GBN + 4];  // Ws[k][n]

    const int tid = threadIdx.x;
    const int tx = tid & 15;
    const int ty = tid >> 4;
    const int bx = blockIdx.x;
    const int by = blockIdx.y;

    const float* Ab = A + (size_t)by * GBM * K;
    const float* Wb = W + (size_t)bx * GBN;

    const int arow = tid >> 2;          // 0..63
    const int acol = (tid & 3) << 2;    // 0,4,8,12
    const int wrow = tid >> 5;          // 0..7
    const int wcol = (tid & 31) << 2;   // 0..124

    float acc[8][8];
#pragma unroll
    for (int i = 0; i < 8; i++)
#pragma unroll
        for (int j = 0; j < 8; j++) acc[i][j] = 0.0f;

    for (int k0 = 0; k0 < K; k0 += GBK) {
#pragma unroll
        for (int r = 0; r < 2; r++) {
            float4 v = *(const float4*)(Ab + (size_t)(arow + r * 64) * K + k0 + acol);
            As[acol + 0][arow + r * 64] = v.x;
            As[acol + 1][arow + r * 64] = v.y;
            As[acol + 2][arow + r * 64] = v.z;
            As[acol + 3][arow + r * 64] = v.w;
        }
#pragma unroll
        for (int r = 0; r < 2; r++) {
            *(float4*)&Ws[wrow + r * 8][wcol] =
                *(const float4*)(Wb + (size_t)(k0 + wrow + r * 8) * N + wcol);
        }
        __syncthreads();

#pragma unroll
        for (int kk = 0; kk < GBK; kk++) {
            float a[8], w[8];
            *(float4*)&a[0] = *(float4*)&As[kk][ty * 8];
            *(float4*)&a[4] = *(float4*)&As[kk][ty * 8 + 4];
            *(float4*)&w[0] = *(float4*)&Ws[kk][tx * 8];
            *(float4*)&w[4] = *(float4*)&Ws[kk][tx * 8 + 4];
#pragma unroll
            for (int i = 0; i < 8; i++)
#pragma unroll
                for (int j = 0; j < 8; j++)
                    acc[i][j] = fmaf(a[i], w[j], acc[i][j]);
        }
        __syncthreads();
    }

    float bcol[8];
    *(float4*)&bcol[0] = *(const float4*)(bias + bx * GBN + tx * 8);
    *(float4*)&bcol[4] = *(const float4*)(bias + bx * GBN + tx * 8 + 4);

#pragma unroll
    for (int i = 0; i < 8; i++) {
        int row = by * GBM + ty * 8 + i;
        float4 o0 = make_float4(acc[i][0] + bcol[0], acc[i][1] + bcol[1],
                                acc[i][2] + bcol[2], acc[i][3] + bcol[3]);
        float4 o1 = make_float4(acc[i][4] + bcol[4], acc[i][5] + bcol[5],
                                acc[i][6] + bcol[6], acc[i][7] + bcol[7]);
        *(float4*)(C + (size_t)row * N + bx * GBN + tx * 8)     = o0;
        *(float4*)(C + (size_t)row * N + bx * GBN + tx * 8 + 4) = o1;
    }
}

// ---------------------------------------------------------------------------
// Causal GQA flash attention (fp32, online softmax).
// Block: one (batch, head, 64-row q tile). 256 threads, 16x16, 4x4 fragments.
// ---------------------------------------------------------------------------
__global__ __launch_bounds__(256) void attn_kernel()
{
    __shared__ float Qs[HEAD_DIM][64 + 4];  // [d][qi]
    __shared__ float Ks[HEAD_DIM][64 + 4];  // [d][kj]
    __shared__ float Vs[64][HEAD_DIM + 4];  // [kj][d]
    __shared__ float Ps[64][64 + 4];        // [kj][qi] (transposed P)

    const int tid = threadIdx.x;
    const int tx = tid & 15;
    const int ty = tid >> 4;
    const int qt = blockIdx.x;
    const int h  = blockIdx.y;
    const int b  = blockIdx.z;
    const int g  = h >> 2;            // KV group
    const int tb = b * TSEQ;

    // Load Q tile (transposed into smem).
    {
        const int row = tid >> 2;                 // 0..63
#pragma unroll
        for (int c = 0; c < 4; c++) {
            const int d = (tid & 3) * 16 + c * 4;
            float4 v = *(const float4*)(g_Q +
                (size_t)(tb + qt * 64 + row) * D_MODEL + h * HEAD_DIM + d);
            Qs[d + 0][row] = v.x;
            Qs[d + 1][row] = v.y;
            Qs[d + 2][row] = v.z;
            Qs[d + 3][row] = v.w;
        }
    }

    float o[4][4];
#pragma unroll
    for (int i = 0; i < 4; i++)
#pragma unroll
        for (int j = 0; j < 4; j++) o[i][j] = 0.0f;
    float m[4] = {-1e30f, -1e30f, -1e30f, -1e30f};
    float l[4] = {0.0f, 0.0f, 0.0f, 0.0f};

    const float scale = 0.125f;  // 1/sqrt(64)
    const int nkt = qt + 1;

    for (int kt = 0; kt < nkt; kt++) {
        __syncthreads();  // protect Ks/Vs/Ps from prior-iteration readers
        // Load K (transposed) and V tiles.
        {
            const int row = tid >> 2;
#pragma unroll
            for (int c = 0; c < 4; c++) {
                const int d = (tid & 3) * 16 + c * 4;
                float4 kv = *(const float4*)(g_K +
                    (size_t)(tb + kt * 64 + row) * KV_DIM + g * HEAD_DIM + d);
                Ks[d + 0][row] = kv.x;
                Ks[d + 1][row] = kv.y;
                Ks[d + 2][row] = kv.z;
                Ks[d + 3][row] = kv.w;
                float4 vv = *(const float4*)(g_V +
                    (size_t)(tb + kt * 64 + row) * KV_DIM + g * HEAD_DIM + d);
                *(float4*)&Vs[row][d] = vv;
            }
        }
        __syncthreads();

        // S = Q @ K^T   (4x4 fragment per thread)
        float s[4][4];
#pragma unroll
        for (int i = 0; i < 4; i++)
#pragma unroll
            for (int j = 0; j < 4; j++) s[i][j] = 0.0f;
#pragma unroll
        for (int d = 0; d < HEAD_DIM; d++) {
            float4 q4 = *(float4*)&Qs[d][ty * 4];
            float4 k4 = *(float4*)&Ks[d][tx * 4];
            float qa[4] = {q4.x, q4.y, q4.z, q4.w};
            float ka[4] = {k4.x, k4.y, k4.z, k4.w};
#pragma unroll
            for (int i = 0; i < 4; i++)
#pragma unroll
                for (int j = 0; j < 4; j++)
                    s[i][j] = fmaf(qa[i], ka[j], s[i][j]);
        }

        // scale + causal mask
        if (kt == qt) {
#pragma unroll
            for (int i = 0; i < 4; i++)
#pragma unroll
                for (int j = 0; j < 4; j++) {
                    int qi = ty * 4 + i, kj = tx * 4 + j;
                    s[i][j] = (kj <= qi) ? s[i][j] * scale : -1e30f;
                }
        } else {
#pragma unroll
            for (int i = 0; i < 4; i++)
#pragma unroll
                for (int j = 0; j < 4; j++) s[i][j] *= scale;
        }

        // Online softmax per row (reduce across the 16 tx lanes).
#pragma unroll
        for (int i = 0; i < 4; i++) {
            float rm = fmaxf(fmaxf(s[i][0], s[i][1]), fmaxf(s[i][2], s[i][3]));
#pragma unroll
            for (int off = 1; off < 16; off <<= 1)
                rm = fmaxf(rm, __shfl_xor_sync(0xffffffffu, rm, off));
            float mn = fmaxf(m[i], rm);
            float corr = __expf(m[i] - mn);
            m[i] = mn;
            float rs = 0.0f;
#pragma unroll
            for (int j = 0; j < 4; j++) {
                float p = __expf(s[i][j] - mn);
                s[i][j] = p;
                rs += p;
            }
#pragma unroll
            for (int off = 1; off < 16; off <<= 1)
                rs += __shfl_xor_sync(0xffffffffu, rs, off);
            l[i] = l[i] * corr + rs;
#pragma unroll
            for (int c = 0; c < 4; c++) o[i][c] *= corr;
        }

        // Store P transposed for the PV GEMM.
#pragma unroll
        for (int i = 0; i < 4; i++)
#pragma unroll
            for (int j = 0; j < 4; j++)
                Ps[tx * 4 + j][ty * 4 + i] = s[i][j];
        __syncthreads();

        // O += P @ V
#pragma unroll
        for (int j = 0; j < 64; j++) {
            float4 p4 = *(float4*)&Ps[j][ty * 4];
            float4 v4 = *(float4*)&Vs[j][tx * 4];
            float pa[4] = {p4.x, p4.y, p4.z, p4.w};
            float va[4] = {v4.x, v4.y, v4.z, v4.w};
#pragma unroll
            for (int i = 0; i < 4; i++)
#pragma unroll
                for (int c = 0; c < 4; c++)
                    o[i][c] = fmaf(pa[i], va[c], o[i][c]);
        }
    }

    // Normalize and write out (layout: [token][head*64 + d]).
#pragma unroll
    for (int i = 0; i < 4; i++) {
        const float inv = 1.0f / l[i];
        const int row = tb + qt * 64 + ty * 4 + i;
        float4 ov = make_float4(o[i][0] * inv, o[i][1] * inv,
                                o[i][2] * inv, o[i][3] * inv);
        *(float4*)(g_O + (size_t)row * D_MODEL + h * HEAD_DIM + tx * 4) = ov;
    }
}

// ---------------------------------------------------------------------------
extern "C" void kernel_launch(void* const* d_in, const int* in_sizes, int n_in,
                              void* d_out, int out_size)
{
    const float* x  = (const float*)d_in[0];
    const float* Wq = (const float*)d_in[1];
    const float* bq = (const float*)d_in[2];
    const float* Wk = (const float*)d_in[3];
    const float* bk = (const float*)d_in[4];
    const float* Wv = (const float*)d_in[5];
    const float* bv = (const float*)d_in[6];
    const float* Wo = (const float*)d_in[7];
    const float* bo = (const float*)d_in[8];
    float* out = (float*)d_out;

    float *Qp, *Kp, *Vp, *Op;
    cudaGetSymbolAddress((void**)&Qp, g_Q);
    cudaGetSymbolAddress((void**)&Kp, g_K);
    cudaGetSymbolAddress((void**)&Vp, g_V);
    cudaGetSymbolAddress((void**)&Op, g_O);

    dim3 blk(256);
    // QKV projections
    sgemm_bias<<<dim3(D_MODEL / GBN, BT / GBM), blk>>>(x, Wq, bq, Qp, BT, D_MODEL, D_MODEL);
    sgemm_bias<<<dim3(KV_DIM  / GBN, BT / GBM), blk>>>(x, Wk, bk, Kp, BT, KV_DIM,  D_MODEL);
    sgemm_bias<<<dim3(KV_DIM  / GBN, BT / GBM), blk>>>(x, Wv, bv, Vp, BT, KV_DIM,  D_MODEL);
    // Causal GQA attention
    attn_kernel<<<dim3(TSEQ / 64, N_HEADS, BATCH), blk>>>();
    // Output projection
    sgemm_bias<<<dim3(D_MODEL / GBN, BT / GBM), blk>>>(Op, Wo, bo, out, BT, D_MODEL, D_MODEL);
}

// round 2
// speedup vs baseline: 1.0032x; 1.0032x over previous
#include <cuda_runtime.h>

#define D_MODEL 1024
#define KV_DIM 256
#define N_HEADS 16
#define N_GROUPS 4
#define HEAD_DIM 64
#define TSEQ 2048
#define BATCH 2
#define BT (BATCH * TSEQ)

// Scratch buffers (static device globals; no allocation in kernel_launch).
__device__ float g_Q[(size_t)BT * D_MODEL];
__device__ float g_K[(size_t)BT * KV_DIM];
__device__ float g_V[(size_t)BT * KV_DIM];
__device__ float g_O[(size_t)BT * D_MODEL];

// ---------------------------------------------------------------------------
// SGEMM: C[M,N] = A[M,K] @ W[K,N] + bias[N]
// 128x128x16 tiles, 256 threads, 8x8 micro-tile per thread.
// ---------------------------------------------------------------------------
#define GBM 128
#define GBN 128
#define GBK 16

__global__ __launch_bounds__(256) void sgemm_bias(
    const float* __restrict__ A, const float* __restrict__ W,
    const float* __restrict__ bias, float* __restrict__ C,
    int M, int N, int K)
{
    __shared__ float As[GBK][GBM + 4];  // transposed A tile: As[k][m]
    __shared__ float Ws[GBK][GBN + 4];  // Ws[k][n]

    const int tid = threadIdx.x;
    const int tx = tid & 15;
    const int ty = tid >> 4;
    const int bx = blockIdx.x;
    const int by = blockIdx.y;

    const float* Ab = A + (size_t)by * GBM * K;
    const float* Wb = W + (size_t)bx * GBN;

    const int arow = tid >> 2;          // 0..63
    const int acol = (tid & 3) << 2;    // 0,4,8,12
    const int wrow = tid >> 5;          // 0..7
    const int wcol = (tid & 31) << 2;   // 0..124

    float acc[8][8];
#pragma unroll
    for (int i = 0; i < 8; i++)
#pragma unroll
        for (int j = 0; j < 8; j++) acc[i][j] = 0.0f;

    for (int k0 = 0; k0 < K; k0 += GBK) {
#pragma unroll
        for (int r = 0; r < 2; r++) {
            float4 v = *(const float4*)(Ab + (size_t)(arow + r * 64) * K + k0 + acol);
            As[acol + 0][arow + r * 64] = v.x;
            As[acol + 1][arow + r * 64] = v.y;
            As[acol + 2][arow + r * 64] = v.z;
            As[acol + 3][arow + r * 64] = v.w;
        }
#pragma unroll
        for (int r = 0; r < 2; r++) {
            *(float4*)&Ws[wrow + r * 8][wcol] =
                *(const float4*)(Wb + (size_t)(k0 + wrow + r * 8) * N + wcol);
        }
        __syncthreads();

#pragma unroll
        for (int kk = 0; kk < GBK; kk++) {
            float a[8], w[8];
            *(float4*)&a[0] = *(float4*)&As[kk][ty * 8];
            *(float4*)&a[4] = *(float4*)&As[kk][ty * 8 + 4];
            *(float4*)&w[0] = *(float4*)&Ws[kk][tx * 8];
            *(float4*)&w[4] = *(float4*)&Ws[kk][tx * 8 + 4];
#pragma unroll
            for (int i = 0; i < 8; i++)
#pragma unroll
                for (int j = 0; j < 8; j++)
                    acc[i][j] = fmaf(a[i], w[j], acc[i][j]);
        }
        __syncthreads();
    }

    float bcol[8];
    *(float4*)&bcol[0] = *(const float4*)(bias + bx * GBN + tx * 8);
    *(float4*)&bcol[4] = *(const float4*)(bias + bx * GBN + tx * 8 + 4);

#pragma unroll
    for (int i = 0; i < 8; i++) {
        int row = by * GBM + ty * 8 + i;
        float4 o0 = make_float4(acc[i][0] + bcol[0], acc[i][1] + bcol[1],
                                acc[i][2] + bcol[2], acc[i][3] + bcol[3]);
        float4 o1 = make_float4(acc[i][4] + bcol[4], acc[i][5] + bcol[5],
                                acc[i][6] + bcol[6], acc[i][7] + bcol[7]);
        *(float4*)(C + (size_t)row * N + bx * GBN + tx * 8)     = o0;
        *(float4*)(C + (size_t)row * N + bx * GBN + tx * 8 + 4) = o1;
    }
}

// ---------------------------------------------------------------------------
// Causal GQA flash attention (fp32, online softmax).
// Block: one (batch, head, 64-row q tile). 256 threads, 16x16, 4x4 fragments.
// ---------------------------------------------------------------------------
__global__ __launch_bounds__(256) void attn_kernel()
{
    __shared__ float Qs[HEAD_DIM][64 + 4];  // [d][qi]
    __shared__ float Ks[HEAD_DIM][64 + 4];  // [d][kj]
    __shared__ float Vs[64][HEAD_DIM + 4];  // [kj][d]
    __shared__ float Ps[64][64 + 4];        // [kj][qi] (transposed P)

    const int tid = threadIdx.x;
    const int tx = tid & 15;
    const int ty = tid >> 4;
    const int qt = blockIdx.x;
    const int h  = blockIdx.y;
    const int b  = blockIdx.z;
    const int g  = h >> 2;            // KV group
    const int tb = b * TSEQ;

    // Load Q tile (transposed into smem).
    {
        const int row = tid >> 2;                 // 0..63
#pragma unroll
        for (int c = 0; c < 4; c++) {
            const int d = (tid & 3) * 16 + c * 4;
            float4 v = *(const float4*)(g_Q +
                (size_t)(tb + qt * 64 + row) * D_MODEL + h * HEAD_DIM + d);
            Qs[d + 0][row] = v.x;
            Qs[d + 1][row] = v.y;
            Qs[d + 2][row] = v.z;
            Qs[d + 3][row] = v.w;
        }
    }

    float o[4][4];
#pragma unroll
    for (int i = 0; i < 4; i++)
#pragma unroll
        for (int j = 0; j < 4; j++) o[i][j] = 0.0f;
    float m[4] = {-1e30f, -1e30f, -1e30f, -1e30f};
    float l[4] = {0.0f, 0.0f, 0.0f, 0.0f};

    const float scale = 0.125f;  // 1/sqrt(64)
    const int nkt = qt + 1;

    for (int kt = 0; kt < nkt; kt++) {
        __syncthreads();  // protect Ks/Vs/Ps from prior-iteration readers
        // Load K (transposed) and V tiles.
        {
            const int row = tid >> 2;
#pragma unroll
            for (int c = 0; c < 4; c++) {
                const int d = (tid & 3) * 16 + c * 4;
                float4 kv = *(const float4*)(g_K +
                    (size_t)(tb + kt * 64 + row) * KV_DIM + g * HEAD_DIM + d);
                Ks[d + 0][row] = kv.x;
                Ks[d + 1][row] = kv.y;
                Ks[d + 2][row] = kv.z;
                Ks[d + 3][row] = kv.w;
                float4 vv = *(const float4*)(g_V +
                    (size_t)(tb + kt * 64 + row) * KV_DIM + g * HEAD_DIM + d);
                *(float4*)&Vs[row][d] = vv;
            }
        }
        __syncthreads();

        // S = Q @ K^T   (4x4 fragment per thread)
        float s[4][4];
#pragma unroll
        for (int i = 0; i < 4; i++)
#pragma unroll
            for (int j = 0; j < 4; j++) s[i][j] = 0.0f;
#pragma unroll
        for (int d = 0; d < HEAD_DIM; d++) {
            float4 q4 = *(float4*)&Qs[d][ty * 4];
            float4 k4 = *(float4*)&Ks[d][tx * 4];
            float qa[4] = {q4.x, q4.y, q4.z, q4.w};
            float ka[4] = {k4.x, k4.y, k4.z, k4.w};
#pragma unroll
            for (int i = 0; i < 4; i++)
#pragma unroll
                for (int j = 0; j < 4; j++)
                    s[i][j] = fmaf(qa[i], ka[j], s[i][j]);
        }

        // scale + causal mask
        if (kt == qt) {
#pragma unroll
            for (int i = 0; i < 4; i++)
#pragma unroll
                for (int j = 0; j < 4; j++) {
                    int qi = ty * 4 + i, kj = tx * 4 + j;
                    s[i][j] = (kj <= qi) ? s[i][j] * scale : -1e30f;
                }
        } else {
#pragma unroll
            for (int i = 0; i < 4; i++)
#pragma unroll
                for (int j = 0; j < 4; j++) s[i][j] *= scale;
        }

        // Online softmax per row (reduce across the 16 tx lanes).
#pragma unroll
        for (int i = 0; i < 4; i++) {
            float rm = fmaxf(fmaxf(s[i][0], s[i][1]), fmaxf(s[i][2], s[i][3]));
#pragma unroll
            for (int off = 1; off < 16; off <<= 1)
                rm = fmaxf(rm, __shfl_xor_sync(0xffffffffu, rm, off));
            float mn = fmaxf(m[i], rm);
            float corr = __expf(m[i] - mn);
            m[i] = mn;
            float rs = 0.0f;
#pragma unroll
            for (int j = 0; j < 4; j++) {
                float p = __expf(s[i][j] - mn);
                s[i][j] = p;
                rs += p;
            }
#pragma unroll
            for (int off = 1; off < 16; off <<= 1)
                rs += __shfl_xor_sync(0xffffffffu, rs, off);
            l[i] = l[i] * corr + rs;
#pragma unroll
            for (int c = 0; c < 4; c++) o[i][c] *= corr;
        }

        // Store P transposed for the PV GEMM.
#pragma unroll
        for (int i = 0; i < 4; i++)
#pragma unroll
            for (int j = 0; j < 4; j++)
                Ps[tx * 4 + j][ty * 4 + i] = s[i][j];
        __syncthreads();

        // O += P @ V
#pragma unroll
        for (int j = 0; j < 64; j++) {
            float4 p4 = *(float4*)&Ps[j][ty * 4];
            float4 v4 = *(float4*)&Vs[j][tx * 4];
            float pa[4] = {p4.x, p4.y, p4.z, p4.w};
            float va[4] = {v4.x, v4.y, v4.z, v4.w};
#pragma unroll
            for (int i = 0; i < 4; i++)
#pragma unroll
                for (int c = 0; c < 4; c++)
                    o[i][c] = fmaf(pa[i], va[c], o[i][c]);
        }
    }

    // Normalize and write out (layout: [token][head*64 + d]).
#pragma unroll
    for (int i = 0; i < 4; i++) {
        const float inv = 1.0f / l[i];
        const int row = tb + qt * 64 + ty * 4 + i;
        float4 ov = make_float4(o[i][0] * inv, o[i][1] * inv,
                                o[i][2] * inv, o[i][3] * inv);
        *(float4*)(g_O + (size_t)row * D_MODEL + h * HEAD_DIM + tx * 4) = ov;
    }
}

// ---------------------------------------------------------------------------
extern "C" void kernel_launch(void* const* d_in, const int* in_sizes, int n_in,
                              void* d_out, int out_size)
{
    const float* x  = (const float*)d_in[0];
    const float* Wq = (const float*)d_in[1];
    const float* bq = (const float*)d_in[2];
    const float* Wk = (const float*)d_in[3];
    const float* bk = (const float*)d_in[4];
    const float* Wv = (const float*)d_in[5];
    const float* bv = (const float*)d_in[6];
    const float* Wo = (const float*)d_in[7];
    const float* bo = (const float*)d_in[8];
    float* out = (float*)d_out;

    float *Qp, *Kp, *Vp, *Op;
    cudaGetSymbolAddress((void**)&Qp, g_Q);
    cudaGetSymbolAddress((void**)&Kp, g_K);
    cudaGetSymbolAddress((void**)&Vp, g_V);
    cudaGetSymbolAddress((void**)&Op, g_O);

    dim3 blk(256);
    // QKV projections
    sgemm_bias<<<dim3(D_MODEL / GBN, BT / GBM), blk>>>(x, Wq, bq, Qp, BT, D_MODEL, D_MODEL);
    sgemm_bias<<<dim3(KV_DIM  / GBN, BT / GBM), blk>>>(x, Wk, bk, Kp, BT, KV_DIM,  D_MODEL);
    sgemm_bias<<<dim3(KV_DIM  / GBN, BT / GBM), blk>>>(x, Wv, bv, Vp, BT, KV_DIM,  D_MODEL);
    // Causal GQA attention
    attn_kernel<<<dim3(TSEQ / 64, N_HEADS, BATCH), blk>>>();
    // Output projection
    sgemm_bias<<<dim3(D_MODEL / GBN, BT / GBM), blk>>>(Op, Wo, bo, out, BT, D_MODEL, D_MODEL);
}

// round 4
// speedup vs baseline: 1.0489x; 1.0456x over previous
#include <cuda_runtime.h>
#include <cstdint>

#define D_MODEL 1024
#define KV_DIM 256
#define N_HEADS 16
#define HEAD_DIM 64
#define TSEQ 2048
#define BATCH 2
#define BT (BATCH * TSEQ)

// Scratch (device globals; no allocation anywhere).
__device__ float g_Q[(size_t)BT * D_MODEL];
__device__ float g_K[(size_t)BT * KV_DIM];
__device__ float g_V[(size_t)BT * KV_DIM];
__device__ float g_O[(size_t)BT * D_MODEL];

// ---------------------------------------------------------------------------
// Helpers
// ---------------------------------------------------------------------------
__device__ __forceinline__ float f2tf32(float v) {
    uint32_t u; asm("cvt.rna.tf32.f32 %0, %1;" : "=r"(u) : "f"(v));
    return __uint_as_float(u);
}

__device__ __forceinline__ void mma1688(float* d, float a0, float a1, float a2,
                                        float a3, float b0, float b1) {
    asm volatile(
        "mma.sync.aligned.m16n8k8.row.col.f32.tf32.tf32.f32 "
        "{%0,%1,%2,%3}, {%4,%5,%6,%7}, {%8,%9}, {%0,%1,%2,%3};"
        : "+f"(d[0]), "+f"(d[1]), "+f"(d[2]), "+f"(d[3])
        : "r"(__float_as_uint(a0)), "r"(__float_as_uint(a1)),
          "r"(__float_as_uint(a2)), "r"(__float_as_uint(a3)),
          "r"(__float_as_uint(b0)), "r"(__float_as_uint(b1)));
}

// ---------------------------------------------------------------------------
// 3xTF32 mma.sync GEMM: C[M,N] = A[M,K] @ W[K,N] + bias
// 128x128x32 CTA tile, 256 threads (8 warps, 2x4), 64x32 warp tile.
// A/B split into tf32 hi/lo at staging; D = AhBh + AhBl + AlBh.
// ---------------------------------------------------------------------------
#define AST 36    // A smem row stride (floats): bank = 4*m + k -> conflict-free
#define BST 132   // B smem row stride (floats): bank = 4*k + n -> conflict-free
#define SM_AH 0
#define SM_AL (128 * AST)
#define SM_BH (2 * 128 * AST)
#define SM_BL (2 * 128 * AST + 32 * BST)
#define SM_FLOATS (2 * 128 * AST + 2 * 32 * BST)

__global__ __launch_bounds__(256) void gemm_mma(
    const float* __restrict__ A, const float* __restrict__ W,
    const float* __restrict__ bias, float* __restrict__ C,
    int M, int N, int K)
{
    extern __shared__ float s[];

    const int tid = threadIdx.x;
    const int lane = tid & 31;
    const int wid = tid >> 5;
    const int wm = (wid >> 2) * 64;       // warp m offset (0,64)
    const int wn = (wid & 3) * 32;        // warp n offset (0,32,64,96)
    const int m0 = blockIdx.y * 128;
    const int n0 = blockIdx.x * 128;

    const int lr = lane >> 2;             // fragment row group 0..7
    const int lc = lane & 3;              // fragment col group 0..3

    // Staging assignments
    const int arow = tid >> 1;            // 0..127
    const int ac0 = (tid & 1) * 16;
    const int brow = tid >> 3;            // 0..31
    const int bc0 = (tid & 7) * 16;

    float acc[4][4][4];
#pragma unroll
    for (int i = 0; i < 4; i++)
#pragma unroll
        for (int j = 0; j < 4; j++)
#pragma unroll
            for (int k = 0; k < 4; k++) acc[i][j][k] = 0.0f;

    const float* Ar = A + (size_t)(m0 + arow) * K;

    for (int kc = 0; kc < K; kc += 32) {
        __syncthreads();   // previous chunk's readers done
        // Stage A[128][32] -> hi/lo
#pragma unroll
        for (int i = 0; i < 4; i++) {
            float4 v = *(const float4*)(Ar + kc + ac0 + i * 4);
            float hx = f2tf32(v.x), hy = f2tf32(v.y),
                  hz = f2tf32(v.z), hw = f2tf32(v.w);
            const int o = arow * AST + ac0 + i * 4;
            s[SM_AH + o + 0] = hx; s[SM_AL + o + 0] = f2tf32(v.x - hx);
            s[SM_AH + o + 1] = hy; s[SM_AL + o + 1] = f2tf32(v.y - hy);
            s[SM_AH + o + 2] = hz; s[SM_AL + o + 2] = f2tf32(v.z - hz);
            s[SM_AH + o + 3] = hw; s[SM_AL + o + 3] = f2tf32(v.w - hw);
        }
        // Stage B[32][128] -> hi/lo
#pragma unroll
        for (int i = 0; i < 4; i++) {
            float4 v = *(const float4*)(W + (size_t)(kc + brow) * N + n0 + bc0 + i * 4);
            float hx = f2tf32(v.x), hy = f2tf32(v.y),
                  hz = f2tf32(v.z), hw = f2tf32(v.w);
            const int o = brow * BST + bc0 + i * 4;
            s[SM_BH + o + 0] = hx; s[SM_BL + o + 0] = f2tf32(v.x - hx);
            s[SM_BH + o + 1] = hy; s[SM_BL + o + 1] = f2tf32(v.y - hy);
            s[SM_BH + o + 2] = hz; s[SM_BL + o + 2] = f2tf32(v.z - hz);
            s[SM_BH + o + 3] = hw; s[SM_BL + o + 3] = f2tf32(v.w - hw);
        }
        __syncthreads();

#pragma unroll
        for (int kk = 0; kk < 4; kk++) {
            const int kb = kk * 8;
            // B fragments for all 4 n-tiles (hi+lo)
            float bh[4][2], bl[4][2];
#pragma unroll
            for (int nt = 0; nt < 4; nt++) {
                const int n = wn + nt * 8 + lr;
                bh[nt][0] = s[SM_BH + (kb + lc) * BST + n];
                bh[nt][1] = s[SM_BH + (kb + 4 + lc) * BST + n];
                bl[nt][0] = s[SM_BL + (kb + lc) * BST + n];
                bl[nt][1] = s[SM_BL + (kb + 4 + lc) * BST + n];
            }
#pragma unroll
            for (int mt = 0; mt < 4; mt++) {
                const int m = wm + mt * 16 + lr;
                float ah0 = s[SM_AH + m * AST + kb + lc];
                float ah1 = s[SM_AH + (m + 8) * AST + kb + lc];
                float ah2 = s[SM_AH + m * AST + kb + 4 + lc];
                float ah3 = s[SM_AH + (m + 8) * AST + kb + 4 + lc];
                float al0 = s[SM_AL + m * AST + kb + lc];
                float al1 = s[SM_AL + (m + 8) * AST + kb + lc];
                float al2 = s[SM_AL + m * AST + kb + 4 + lc];
                float al3 = s[SM_AL + (m + 8) * AST + kb + 4 + lc];
#pragma unroll
                for (int nt = 0; nt < 4; nt++) {
                    mma1688(acc[mt][nt], ah0, ah1, ah2, ah3, bh[nt][0], bh[nt][1]);
                    mma1688(acc[mt][nt], ah0, ah1, ah2, ah3, bl[nt][0], bl[nt][1]);
                    mma1688(acc[mt][nt], al0, al1, al2, al3, bh[nt][0], bh[nt][1]);
                }
            }
        }
    }

    // Epilogue: add bias, write C.
#pragma unroll
    for (int nt = 0; nt < 4; nt++) {
        const int n = n0 + wn + nt * 8 + lc * 2;
        const float2 bv = *(const float2*)(bias + n);
#pragma unroll
        for (int mt = 0; mt < 4; mt++) {
            const int m = m0 + wm + mt * 16 + lr;
            float2 o0 = make_float2(acc[mt][nt][0] + bv.x, acc[mt][nt][1] + bv.y);
            float2 o1 = make_float2(acc[mt][nt][2] + bv.x, acc[mt][nt][3] + bv.y);
            *(float2*)(C + (size_t)m * N + n) = o0;
            *(float2*)(C + (size_t)(m + 8) * N + n) = o1;
        }
    }
}

// ---------------------------------------------------------------------------
// Causal GQA flash attention (fp32, online softmax). Unchanged (proven).
// ---------------------------------------------------------------------------
__global__ __launch_bounds__(256) void attn_kernel()
{
    __shared__ float Qs[HEAD_DIM][64 + 4];
    __shared__ float Ks[HEAD_DIM][64 + 4];
    __shared__ float Vs[64][HEAD_DIM + 4];
    __shared__ float Ps[64][64 + 4];

    const int tid = threadIdx.x;
    const int tx = tid & 15;
    const int ty = tid >> 4;
    const int qt = blockIdx.x;
    const int h  = blockIdx.y;
    const int b  = blockIdx.z;
    const int g  = h >> 2;
    const int tb = b * TSEQ;

    {
        const int row = tid >> 2;
#pragma unroll
        for (int c = 0; c < 4; c++) {
            const int d = (tid & 3) * 16 + c * 4;
            float4 v = *(const float4*)(g_Q +
                (size_t)(tb + qt * 64 + row) * D_MODEL + h * HEAD_DIM + d);
            Qs[d + 0][row] = v.x;
            Qs[d + 1][row] = v.y;
            Qs[d + 2][row] = v.z;
            Qs[d + 3][row] = v.w;
        }
    }

    float o[4][4];
#pragma unroll
    for (int i = 0; i < 4; i++)
#pragma unroll
        for (int j = 0; j < 4; j++) o[i][j] = 0.0f;
    float m[4] = {-1e30f, -1e30f, -1e30f, -1e30f};
    float l[4] = {0.0f, 0.0f, 0.0f, 0.0f};

    const float scale = 0.125f;
    const int nkt = qt + 1;

    for (int kt = 0; kt < nkt; kt++) {
        __syncthreads();
        {
            const int row = tid >> 2;
#pragma unroll
            for (int c = 0; c < 4; c++) {
                const int d = (tid & 3) * 16 + c * 4;
                float4 kv = *(const float4*)(g_K +
                    (size_t)(tb + kt * 64 + row) * KV_DIM + g * HEAD_DIM + d);
                Ks[d + 0][row] = kv.x;
                Ks[d + 1][row] = kv.y;
                Ks[d + 2][row] = kv.z;
                Ks[d + 3][row] = kv.w;
                float4 vv = *(const float4*)(g_V +
                    (size_t)(tb + kt * 64 + row) * KV_DIM + g * HEAD_DIM + d);
                *(float4*)&Vs[row][d] = vv;
            }
        }
        __syncthreads();

        float sf[4][4];
#pragma unroll
        for (int i = 0; i < 4; i++)
#pragma unroll
            for (int j = 0; j < 4; j++) sf[i][j] = 0.0f;
#pragma unroll
        for (int d = 0; d < HEAD_DIM; d++) {
            float4 q4 = *(float4*)&Qs[d][ty * 4];
            float4 k4 = *(float4*)&Ks[d][tx * 4];
            float qa[4] = {q4.x, q4.y, q4.z, q4.w};
            float ka[4] = {k4.x, k4.y, k4.z, k4.w};
#pragma unroll
            for (int i = 0; i < 4; i++)
#pragma unroll
                for (int j = 0; j < 4; j++)
                    sf[i][j] = fmaf(qa[i], ka[j], sf[i][j]);
        }

        if (kt == qt) {
#pragma unroll
            for (int i = 0; i < 4; i++)
#pragma unroll
                for (int j = 0; j < 4; j++) {
                    int qi = ty * 4 + i, kj = tx * 4 + j;
                    sf[i][j] = (kj <= qi) ? sf[i][j] * scale : -1e30f;
                }
        } else {
#pragma unroll
            for (int i = 0; i < 4; i++)
#pragma unroll
                for (int j = 0; j < 4; j++) sf[i][j] *= scale;
        }

#pragma unroll
        for (int i = 0; i < 4; i++) {
            float rm = fmaxf(fmaxf(sf[i][0], sf[i][1]), fmaxf(sf[i][2], sf[i][3]));
#pragma unroll
            for (int off = 1; off < 16; off <<= 1)
                rm = fmaxf(rm, __shfl_xor_sync(0xffffffffu, rm, off));
            float mn = fmaxf(m[i], rm);
            float corr = __expf(m[i] - mn);
            m[i] = mn;
            float rs = 0.0f;
#pragma unroll
            for (int j = 0; j < 4; j++) {
                float p = __expf(sf[i][j] - mn);
                sf[i][j] = p;
                rs += p;
            }
#pragma unroll
            for (int off = 1; off < 16; off <<= 1)
                rs += __shfl_xor_sync(0xffffffffu, rs, off);
            l[i] = l[i] * corr + rs;
#pragma unroll
            for (int c = 0; c < 4; c++) o[i][c] *= corr;
        }

#pragma unroll
        for (int i = 0; i < 4; i++)
#pragma unroll
            for (int j = 0; j < 4; j++)
                Ps[tx * 4 + j][ty * 4 + i] = sf[i][j];
        __syncthreads();

#pragma unroll
        for (int j = 0; j < 64; j++) {
            float4 p4 = *(float4*)&Ps[j][ty * 4];
            float4 v4 = *(float4*)&Vs[j][tx * 4];
            float pa[4] = {p4.x, p4.y, p4.z, p4.w};
            float va[4] = {v4.x, v4.y, v4.z, v4.w};
#pragma unroll
            for (int i = 0; i < 4; i++)
#pragma unroll
                for (int c = 0; c < 4; c++)
                    o[i][c] = fmaf(pa[i], va[c], o[i][c]);
        }
    }

#pragma unroll
    for (int i = 0; i < 4; i++) {
        const float inv = 1.0f / l[i];
        const int row = tb + qt * 64 + ty * 4 + i;
        float4 ov = make_float4(o[i][0] * inv, o[i][1] * inv,
                                o[i][2] * inv, o[i][3] * inv);
        *(float4*)(g_O + (size_t)row * D_MODEL + h * HEAD_DIM + tx * 4) = ov;
    }
}

// ---------------------------------------------------------------------------
extern "C" void kernel_launch(void* const* d_in, const int* in_sizes, int n_in,
                              void* d_out, int out_size)
{
    const float* x  = (const float*)d_in[0];
    const float* Wq = (const float*)d_in[1];
    const float* bq = (const float*)d_in[2];
    const float* Wk = (const float*)d_in[3];
    const float* bk = (const float*)d_in[4];
    const float* Wv = (const float*)d_in[5];
    const float* bv = (const float*)d_in[6];
    const float* Wo = (const float*)d_in[7];
    const float* bo = (const float*)d_in[8];
    float* out = (float*)d_out;

    float *Qp, *Kp, *Vp, *Op;
    cudaGetSymbolAddress((void**)&Qp, g_Q);
    cudaGetSymbolAddress((void**)&Kp, g_K);
    cudaGetSymbolAddress((void**)&Vp, g_V);
    cudaGetSymbolAddress((void**)&Op, g_O);

    const int dyn = SM_FLOATS * 4;   // 70656 bytes
    cudaFuncSetAttribute(gemm_mma,
                         cudaFuncAttributeMaxDynamicSharedMemorySize, dyn);

    // QKV projections (mma.sync tf32, 3x-split accuracy)
    gemm_mma<<<dim3(D_MODEL / 128, BT / 128), 256, dyn>>>(x, Wq, bq, Qp, BT, D_MODEL, D_MODEL);
    gemm_mma<<<dim3(KV_DIM  / 128, BT / 128), 256, dyn>>>(x, Wk, bk, Kp, BT, KV_DIM,  D_MODEL);
    gemm_mma<<<dim3(KV_DIM  / 128, BT / 128), 256, dyn>>>(x, Wv, bv, Vp, BT, KV_DIM,  D_MODEL);

    // Causal GQA attention
    attn_kernel<<<dim3(TSEQ / 64, N_HEADS, BATCH), 256>>>();

    // Output projection
    gemm_mma<<<dim3(D_MODEL / 128, BT / 128), 256, dyn>>>(Op, Wo, bo, out, BT, D_MODEL, D_MODEL);
}